// round 10
// baseline (speedup 1.0000x reference)
#include <cuda_runtime.h>
#include <cuda_bf16.h>
#include <cstdint>

#define B 8
#define S 2048
#define H 2048
#define A 8192

// output section offsets (element counts, float32)
#define OUT0 0ULL                               // x*best_path  [B*S*H]
#define OUT1 (OUT0 + (size_t)B * S * H)         // new_trails   [H*H]
#define OUT2 (OUT1 + (size_t)H * H)             // new_paths    [A*H]
#define OUT3 (OUT2 + (size_t)A * H)             // new_best_len [1]
#define OUT4 (OUT3 + 1ULL)                      // next_pos     [A] (as f32)

#define TRAIL_BLOCKS (H * H / 4 / 256 / 2)          // 2048 (2 float4/thread)
#define OUT_BLOCKS   ((B * S * H) / 4 / 256 / 4)    // 8192  (4 float4/thread)

// ---------------- device scratch (no allocations allowed) ----------------
__device__ float g_diag[H];
__device__ float g_rowmax[H];
__device__ float g_rowlse[H];
__device__ int   g_rowconst[H];
__device__ unsigned long long g_minkey;   // (len_bits<<32)|ant : atomicMin argmin

// mad.lo with an opaque 'one' (kernel param) -> IMAD on the fma pipe.
__device__ __forceinline__ uint32_t madd(uint32_t one, uint32_t a, uint32_t b) {
    uint32_t r;
    asm("mad.lo.s32 %0, %1, %2, %3;" : "=r"(r) : "r"(one), "r"(a), "r"(b));
    return r;
}

// ---------------- threefry2x32, key = (0, 42) (20 rounds) -----------------
// returns raw lane outputs; caller combines (x0 ^ x1)
__device__ __forceinline__ void threefry_raw(uint32_t one, uint32_t i,
                                             uint32_t& ox0, uint32_t& ox1) {
    const uint32_t k0 = 0u, k1 = 42u;
    const uint32_t k2 = k0 ^ k1 ^ 0x1BD11BDAu;
    uint32_t x0 = k0, x1 = madd(one, i, k1);
#define TF_R(r) { x0 = madd(one, x1, x0); x1 = __funnelshift_l(x1, x1, (r)); x1 ^= x0; }
    TF_R(13) TF_R(15) TF_R(26) TF_R(6)
    x0 = madd(one, k1, x0); x1 = madd(one, k2 + 1u, x1);
    TF_R(17) TF_R(29) TF_R(16) TF_R(24)
    x0 = madd(one, k2, x0); x1 = madd(one, k0 + 2u, x1);
    TF_R(13) TF_R(15) TF_R(26) TF_R(6)
    x0 = madd(one, k0, x0); x1 = madd(one, k1 + 3u, x1);
    TF_R(17) TF_R(29) TF_R(16) TF_R(24)
    x0 = madd(one, k1, x0); x1 = madd(one, k2 + 4u, x1);
    TF_R(13) TF_R(15) TF_R(26) TF_R(6)
    x0 = madd(one, k2, x0); x1 = madd(one, k0 + 5u, x1);
#undef TF_R
    ox0 = x0; ox1 = x1;
}

__device__ __forceinline__ float gumbel_from_bits(uint32_t bits) {
    float f = __uint_as_float((bits >> 9) | 0x3F800000u) - 1.0f;
    const float tiny = 1.17549435e-38f;
    float u = fmaxf(tiny, f * (1.0f - tiny) + tiny);
    float t = -__logf(u);
    return -__logf(t);
}

// ---------------- K0: 4 warps/row, 2 rows/block, running max/min -----------
// grid = H/2 = 1024 blocks of 256 threads. lse only for non-const rows.
__global__ void __launch_bounds__(256)
k0_rowstats(const float* __restrict__ trails) {
    __shared__ float wmax[8], wmin[8];
    __shared__ float cmax[2], cmin[2];
    __shared__ float wsum[8];
    int warp = threadIdx.x >> 5;
    int lane = threadIdx.x & 31;
    int rloc = warp >> 2;                 // 0..1 row within block
    int wsub = warp & 3;                  // quarter of the row
    int r = blockIdx.x * 2 + rloc;
    const float4* q4 = reinterpret_cast<const float4*>(trails + (size_t)r * H)
                     + wsub * 128 + lane;
    float4 v0 = q4[0], v1 = q4[32], v2 = q4[64], v3 = q4[96];
    float m  = fmaxf(fmaxf(fmaxf(v0.x, v0.y), fmaxf(v0.z, v0.w)),
                     fmaxf(fmaxf(fmaxf(v1.x, v1.y), fmaxf(v1.z, v1.w)),
                           fmaxf(fmaxf(fmaxf(v2.x, v2.y), fmaxf(v2.z, v2.w)),
                                 fmaxf(fmaxf(v3.x, v3.y), fmaxf(v3.z, v3.w)))));
    float mn = fminf(fminf(fminf(v0.x, v0.y), fminf(v0.z, v0.w)),
                     fminf(fminf(fminf(v1.x, v1.y), fminf(v1.z, v1.w)),
                           fminf(fminf(fminf(v2.x, v2.y), fminf(v2.z, v2.w)),
                                 fminf(fminf(v3.x, v3.y), fminf(v3.z, v3.w)))));
    #pragma unroll
    for (int s = 16; s > 0; s >>= 1) {
        m  = fmaxf(m,  __shfl_xor_sync(0xFFFFFFFFu, m,  s));
        mn = fminf(mn, __shfl_xor_sync(0xFFFFFFFFu, mn, s));
    }
    if (lane == 0) { wmax[warp] = m; wmin[warp] = mn; }
    __syncthreads();
    if (warp == 0 && lane < 2) {
        int base = lane * 4;
        float M  = fmaxf(fmaxf(wmax[base], wmax[base + 1]),
                         fmaxf(wmax[base + 2], wmax[base + 3]));
        float MN = fminf(fminf(wmin[base], wmin[base + 1]),
                         fminf(wmin[base + 2], wmin[base + 3]));
        cmax[lane] = M; cmin[lane] = MN;
        int rr = blockIdx.x * 2 + lane;
        g_rowmax[rr] = M;
        g_rowconst[rr] = (M == MN);
        g_diag[rr] = 0.0f;
        if (rr == 0) g_minkey = ~0ULL;
    }
    __syncthreads();
    float M = cmax[rloc];
    if (M != cmin[rloc]) {    // non-const row: lse pass (values still in regs)
        float sum = expf(v0.x - M) + expf(v0.y - M) + expf(v0.z - M) + expf(v0.w - M)
                  + expf(v1.x - M) + expf(v1.y - M) + expf(v1.z - M) + expf(v1.w - M)
                  + expf(v2.x - M) + expf(v2.y - M) + expf(v2.z - M) + expf(v2.w - M)
                  + expf(v3.x - M) + expf(v3.y - M) + expf(v3.z - M) + expf(v3.w - M);
        #pragma unroll
        for (int s = 16; s > 0; s >>= 1)
            sum += __shfl_xor_sync(0xFFFFFFFFu, sum, s);
        if (lane == 0) wsum[warp] = sum;
        __syncthreads();
        if (wsub == 0 && lane == 0) {
            int base = rloc * 4;
            g_rowlse[r] = logf(wsum[base] + wsum[base + 1]
                             + wsum[base + 2] + wsum[base + 3]);
        }
    }
}

// ---------------- K12: sampling + paths + lengths + diag + zero out0 -------
// thread-contiguous layout: thread tid owns h = tid*8 .. tid*8+7
__global__ void __launch_bounds__(256)
k12_sample_paths(const float* __restrict__ trails,
                 const float* __restrict__ ant_paths,
                 const int* __restrict__ ant_positions,
                 const float* __restrict__ strength_p,
                 float* __restrict__ out2,
                 float* __restrict__ out4,
                 float* __restrict__ out0,
                 uint32_t one) {
    __shared__ float sv[256];
    __shared__ int   si[256];
    __shared__ float ss[256];
    __shared__ float s_upd;
    __shared__ int   s_np;
    int a = blockIdx.x;
    int tid = threadIdx.x;
    int p = ant_positions[a];
    const float* prow = ant_paths + (size_t)a * H;
    float* orow = out2 + (size_t)a * H;

    // zero a 16KB slice of out0 (hidden under this kernel's ALU shadow)
    {
        float4* z4 = reinterpret_cast<float4*>(out0 + (size_t)a * 4096) + tid;
        const float4 zz = make_float4(0.0f, 0.0f, 0.0f, 0.0f);
        #pragma unroll
        for (int j = 0; j < 4; j++) z4[j * 256] = zz;
    }

    // path row: 8 contiguous floats per thread, float4 I/O
    const float4* p4 = reinterpret_cast<const float4*>(prow) + tid * 2;
    float4* o4 = reinterpret_cast<float4*>(orow) + tid * 2;
    float4 pv0 = p4[0], pv1 = p4[1];
    o4[0] = pv0; o4[1] = pv1;
    float sumsq = pv0.x * pv0.x + pv0.y * pv0.y + pv0.z * pv0.z + pv0.w * pv0.w
                + pv1.x * pv1.x + pv1.y * pv1.y + pv1.z * pv1.z + pv1.w * pv1.w;
    uint32_t mask = 0;   // bit k <=> prow[tid*8+k] > 0
    if (pv0.x > 0.0f) mask |= 1u;  if (pv0.y > 0.0f) mask |= 2u;
    if (pv0.z > 0.0f) mask |= 4u;  if (pv0.w > 0.0f) mask |= 8u;
    if (pv1.x > 0.0f) mask |= 16u; if (pv1.y > 0.0f) mask |= 32u;
    if (pv1.z > 0.0f) mask |= 64u; if (pv1.w > 0.0f) mask |= 128u;

    float bvf;
    int   bi;
    uint32_t ibase = (uint32_t)a * H + (uint32_t)tid * 8u;

    if (g_rowconst[p]) {
        // constant logits: argmax z == argmax (bits>>9).
        // (x0^x1)&C is ONE LOP3; low 9 bits vacant -> '+(7-k)' (any pipe).
        // max w == max z with smallest k on z-ties (fields differ by >=512).
        uint32_t bw = 0u;
        #pragma unroll
        for (uint32_t k = 0; k < 8; k++) {
            uint32_t x0, x1;
            threefry_raw(one, ibase + k, x0, x1);
            uint32_t w = ((x0 ^ x1) & 0xFFFFFE00u) + (7u - k);
            bw = max(bw, w);
        }
        bvf = (float)(bw >> 9);               // exact (23-bit)
        bi  = tid * 8 + (int)(7u - (bw & 7u));
    } else {
        const float* trow = trails + (size_t)p * H;
        float rm = g_rowmax[p], rl = g_rowlse[p];
        bvf = -__int_as_float(0x7f800000); bi = 0;
        #pragma unroll
        for (uint32_t k = 0; k < 8; k++) {
            int h = tid * 8 + k;
            uint32_t x0, x1;
            threefry_raw(one, ibase + k, x0, x1);
            float z = gumbel_from_bits(x0 ^ x1) + ((trow[h] - rm) - rl);
            if (z > bvf) { bvf = z; bi = h; }  // h increasing -> first index kept
        }
    }

    // cross-thread reduce: (z, h) with first-index (smallest h) tie-break
    sv[tid] = bvf; si[tid] = bi; ss[tid] = sumsq; __syncthreads();
    for (int s = 128; s > 0; s >>= 1) {
        if (tid < s) {
            float v2 = sv[tid + s]; int i2 = si[tid + s];
            if (v2 > sv[tid] || (v2 == sv[tid] && i2 < si[tid])) { sv[tid] = v2; si[tid] = i2; }
            ss[tid] += ss[tid + s];
        }
        __syncthreads();
    }
    if (tid == 0) {
        int np = si[0];
        float old = prow[np];
        float len = sqrtf(ss[0] - old * old + 1.0f);   // one-hot substitution
        // global argmin: len>=0 -> float order == uint bit order; low word = ant
        unsigned long long key =
            ((unsigned long long)__float_as_uint(len) << 32) | (unsigned)a;
        atomicMin(&g_minkey, key);
        s_np = np;
        s_upd = strength_p[0] / (len + 1e-8f);
        out4[a] = (float)np;
    }
    __syncthreads();
    float upd = s_upd;
    int np = s_np;
    // sparse diag fixups only (stores already done above)
    if (mask) {
        #pragma unroll
        for (uint32_t k = 0; k < 8; k++)
            if (mask & (1u << k)) atomicAdd(&g_diag[tid * 8 + k], upd);
    }
    if (tid == 0) {
        orow[np] = 1.0f;                       // after __syncthreads: ordered
        if (!(prow[np] > 0.0f)) atomicAdd(&g_diag[np], upd);
    }
}

// ---------------- K56: trails + best-len + SPARSE broadcast multiply -------
// out0 already zeroed by k12: x-section only touches chunks where bp != 0.
__global__ void __launch_bounds__(256)
k56_finish(const float* __restrict__ trails,
           const float* __restrict__ decay_p,
           const float* __restrict__ x,
           const float* __restrict__ bpl_p,
           const float* __restrict__ best_path_in,
           const float* __restrict__ new_paths_out,
           float* __restrict__ out1,
           float* __restrict__ out0,
           float* __restrict__ out3) {
    int b = blockIdx.x;
    int tid = threadIdx.x;
    if (b < TRAIL_BLOCKS) {
        float dec = 1.0f - decay_p[0];
        size_t base = (size_t)b * 256 + tid;
        #pragma unroll
        for (int j = 0; j < 2; j++) {
            size_t idx4 = (base + (size_t)j * TRAIL_BLOCKS * 256) * 4;
            int i  = (int)(idx4 >> 11);       // row
            int j0 = (int)(idx4 & (H - 1));
            const float4 t = *reinterpret_cast<const float4*>(trails + idx4);
            float d = g_diag[i];
            float4 o;
            o.x = (t.x + (i == (j0 + 0) ? d : 0.0f)) * dec;
            o.y = (t.y + (i == (j0 + 1) ? d : 0.0f)) * dec;
            o.z = (t.z + (i == (j0 + 2) ? d : 0.0f)) * dec;
            o.w = (t.w + (i == (j0 + 3) ? d : 0.0f)) * dec;
            *reinterpret_cast<float4*>(out1 + idx4) = o;
        }
    } else {
        // resolve best path inline
        unsigned long long key = g_minkey;
        float blen = __uint_as_float((unsigned)(key >> 32));
        int   best = (int)(unsigned)(key & 0xFFFFFFFFu);
        float bpl  = bpl_p[0];
        int improved = blen < bpl;
        if (b == TRAIL_BLOCKS && tid == 0) out3[0] = improved ? blen : bpl;
        const float* src = improved ? (new_paths_out + (size_t)best * H)
                                    : best_path_in;   // 8KB, L1/L2-hot broadcast
        size_t base = (size_t)(b - TRAIL_BLOCKS) * 256 + tid;
        #pragma unroll
        for (int j = 0; j < 4; j++) {
            size_t idx4 = (base + (size_t)j * OUT_BLOCKS * 256) * 4;
            int h0 = (int)(idx4 & (H - 1));
            const float4 bp = *reinterpret_cast<const float4*>(src + h0);
            if (bp.x != 0.0f || bp.y != 0.0f || bp.z != 0.0f || bp.w != 0.0f) {
                const float4 xv = *reinterpret_cast<const float4*>(x + idx4);
                float4 o;
                o.x = xv.x * bp.x;
                o.y = xv.y * bp.y;
                o.z = xv.z * bp.z;
                o.w = xv.w * bp.w;
                *reinterpret_cast<float4*>(out0 + idx4) = o;
            }
            // else: out0 chunk already zeroed by k12
        }
    }
}

extern "C" void kernel_launch(void* const* d_in, const int* in_sizes, int n_in,
                              void* d_out, int out_size) {
    const float* x        = (const float*)d_in[0];
    const float* trails   = (const float*)d_in[1];
    const float* paths    = (const float*)d_in[2];
    const float* bestpath = (const float*)d_in[3];
    const float* bpl      = (const float*)d_in[4];
    const float* decay    = (const float*)d_in[5];
    const float* strength = (const float*)d_in[6];
    const int*   antpos   = (const int*)d_in[7];
    float* out = (float*)d_out;

    k0_rowstats<<<H / 2, 256>>>(trails);
    k12_sample_paths<<<A, 256>>>(trails, paths, antpos, strength,
                                 out + OUT2, out + OUT4, out + OUT0, 1u);
    k56_finish<<<TRAIL_BLOCKS + OUT_BLOCKS, 256>>>(trails, decay, x, bpl,
                                                   bestpath, out + OUT2,
                                                   out + OUT1, out + OUT0,
                                                   out + OUT3);
}